// round 4
// baseline (speedup 1.0000x reference)
#include <cuda_runtime.h>
#include <cuda_fp16.h>
#include <cstdint>
#include <math.h>

#define DEVINL __device__ __forceinline__

// ---------------- dims ----------------
constexpr int BDIM = 4096, HDIM = 4096, VDIM = 4096;
constexpr int KH_GATES = VDIM + HDIM;   // 8192
constexpr int NTOT_GATES = 4 * HDIM;    // 16384 (f,i,c,o stacked)

// ---------------- scratch (__device__ globals; no allocations) ----------------
__device__ __half g_xh  [(size_t)BDIM * KH_GATES];          // 64 MB
__device__ __half g_wall[(size_t)4 * HDIM * KH_GATES];      // 256 MB
__device__ __half g_wout[(size_t)VDIM * HDIM];              // 32 MB
__device__ float  g_pre [(size_t)BDIM * NTOT_GATES];        // 256 MB
__device__ __half g_h16 [(size_t)BDIM * HDIM];              // 32 MB

// ---------------- small helpers ----------------
DEVINL uint32_t smem_u32(const void* p) {
    uint32_t a;
    asm("{ .reg .u64 t; cvta.to.shared.u64 t, %1; cvt.u32.u64 %0, t; }"
        : "=r"(a) : "l"(p));
    return a;
}
DEVINL void cp16(uint32_t dst, const void* src) {
    asm volatile("cp.async.cg.shared.global [%0], [%1], 16;"
                 :: "r"(dst), "l"(__cvta_generic_to_global(src)) : "memory");
}
DEVINL void ldsm4(uint32_t (&r)[4], uint32_t addr) {
    asm volatile("ldmatrix.sync.aligned.m8n8.x4.shared.b16 {%0,%1,%2,%3}, [%4];"
                 : "=r"(r[0]), "=r"(r[1]), "=r"(r[2]), "=r"(r[3]) : "r"(addr));
}
DEVINL void mma16816(float (&d)[4], const uint32_t (&a)[4], uint32_t b0, uint32_t b1) {
    asm volatile(
        "mma.sync.aligned.m16n8k16.row.col.f32.f16.f16.f32 "
        "{%0,%1,%2,%3},{%4,%5,%6,%7},{%8,%9},{%0,%1,%2,%3};"
        : "+f"(d[0]), "+f"(d[1]), "+f"(d[2]), "+f"(d[3])
        : "r"(a[0]), "r"(a[1]), "r"(a[2]), "r"(a[3]), "r"(b0), "r"(b1));
}
DEVINL uint32_t f2h2(float a, float b) {
    __half2 t = __floats2half2_rn(a, b);
    return *reinterpret_cast<uint32_t*>(&t);
}
DEVINL float sig(float x) { return 1.0f / (1.0f + expf(-x)); }

// ---------------- conversion kernels ----------------
// pack [x | h] rows into fp16 g_xh; one thread = 8 halves (16B out)
__global__ void __launch_bounds__(256) pack_xh(const float* __restrict__ x,
                                               const float* __restrict__ h) {
    const size_t o8 = (size_t)blockIdx.x * 256 + threadIdx.x;   // grid 16384
    const int    k8 = (int)(o8 & 1023);                         // 8192/8
    const size_t m  = o8 >> 10;
    const float* s  = (k8 < 512) ? x + m * VDIM + (size_t)k8 * 8
                                 : h + m * HDIM + (size_t)(k8 - 512) * 8;
    const float4 a = *(const float4*)s;
    const float4 b = *(const float4*)(s + 4);
    uint4 o;
    o.x = f2h2(a.x, a.y); o.y = f2h2(a.z, a.w);
    o.z = f2h2(b.x, b.y); o.w = f2h2(b.z, b.w);
    ((uint4*)g_xh)[o8] = o;
}

// convert one fp32 weight matrix to fp16; which 0..3 -> g_wall slice, 4 -> g_wout
__global__ void __launch_bounds__(256) conv_w(const float* __restrict__ s, int which) {
    const size_t i8 = (size_t)blockIdx.x * 256 + threadIdx.x;
    __half* dst = (which < 4) ? g_wall + ((size_t)which << 25) : g_wout;
    const float4 a = *(const float4*)(s + i8 * 8);
    const float4 b = *(const float4*)(s + i8 * 8 + 4);
    uint4 o;
    o.x = f2h2(a.x, a.y); o.y = f2h2(a.z, a.w);
    o.z = f2h2(b.x, b.y); o.w = f2h2(b.z, b.w);
    ((uint4*)dst)[i8] = o;
}

// ---------------- GEMM: C[M,NTOT] = A[M,K] * B[NTOT,K]^T (fp16 in, fp32 out) ----
// MODE 0: A=g_xh K=8192, B=g_wall NTOT=16384, C=g_pre      (no bias)
// MODE 1: A=g_h16 K=4096, B=g_wout NTOT=4096,  C=out+bias
template <int MODE>
__global__ void __launch_bounds__(256, 1) gemm_f16(float* __restrict__ Cext,
                                                   const float* __restrict__ bias) {
    constexpr int KH     = MODE ? HDIM : KH_GATES;
    constexpr int NTOT   = MODE ? VDIM : NTOT_GATES;
    constexpr int KTILES = KH / 64;
    const __half* A  = MODE ? g_h16 : g_xh;
    const __half* Bw = MODE ? g_wout : g_wall;
    float* C = MODE ? Cext : g_pre;

    extern __shared__ char smem[];                 // 4 stages x (16KB A + 16KB B)
    const uint32_t sb = smem_u32(smem);
    const int tid = threadIdx.x, lane = tid & 31, wid = tid >> 5;
    const int wm = wid & 1, wn = wid >> 1;         // warp grid 2(M) x 4(N)
    const int m0 = blockIdx.x * 128, n0 = blockIdx.y * 128;

    auto load_stage = [&](int kt, int s) {
        const int kg = kt * 64;                    // halves
        #pragma unroll
        for (int it = 0; it < 8; it++) {
            const int chunk = tid + it * 256;      // 2048 x 16B per stage
            const int seg = chunk >> 10;           // 0=A 1=B
            const int w = chunk & 1023;
            const int row = w >> 3, cc = w & 7;
            const __half* src = (seg == 0)
                ? A  + (size_t)(m0 + row) * KH + kg + cc * 8
                : Bw + (size_t)(n0 + row) * KH + kg + cc * 8;
            cp16(sb + s * 32768 + seg * 16384 + row * 128 + ((cc ^ (row & 7)) << 4), src);
        }
        asm volatile("cp.async.commit_group;" ::: "memory");
    };

    load_stage(0, 0); load_stage(1, 1); load_stage(2, 2);

    // per-thread ldmatrix bases (row & 7 == lane & 7 for all fragments)
    uint32_t a_base[4], b_base[2];
    #pragma unroll
    for (int im = 0; im < 4; im++)
        a_base[im] = sb + (uint32_t)((wm * 64 + im * 16 + (lane & 15)) * 128);
    #pragma unroll
    for (int ig = 0; ig < 2; ig++)
        b_base[ig] = sb + 16384 +
            (uint32_t)((wn * 32 + ig * 16 + (lane & 7) + ((lane >> 1) & 8)) * 128);
    const int a_hi = lane >> 4;
    const int b_hi = (lane >> 3) & 1;
    const int sxor = lane & 7;

    float acc[4][4][4];
    #pragma unroll
    for (int i = 0; i < 4; i++)
        #pragma unroll
        for (int j = 0; j < 4; j++)
            #pragma unroll
            for (int k = 0; k < 4; k++) acc[i][j][k] = 0.0f;

    for (int kt = 0; kt < KTILES; kt++) {
        asm volatile("cp.async.wait_group 2;" ::: "memory");
        __syncthreads();
        if (kt + 3 < KTILES) load_stage(kt + 3, (kt + 3) & 3);
        else asm volatile("cp.async.commit_group;" ::: "memory");

        const uint32_t soff = (uint32_t)((kt & 3) * 32768);
        #pragma unroll
        for (int ks = 0; ks < 4; ks++) {
            uint32_t a[4][4], b[2][4];
            #pragma unroll
            for (int im = 0; im < 4; im++)
                ldsm4(a[im], a_base[im] + soff + (uint32_t)(((ks * 2 + a_hi) ^ sxor) << 4));
            #pragma unroll
            for (int ig = 0; ig < 2; ig++)
                ldsm4(b[ig], b_base[ig] + soff + (uint32_t)(((ks * 2 + b_hi) ^ sxor) << 4));
            #pragma unroll
            for (int im = 0; im < 4; im++)
                #pragma unroll
                for (int ig = 0; ig < 2; ig++) {
                    mma16816(acc[im][2 * ig + 0], a[im], b[ig][0], b[ig][1]);
                    mma16816(acc[im][2 * ig + 1], a[im], b[ig][2], b[ig][3]);
                }
        }
    }

    const int rbase = lane >> 2, c2 = (lane & 3) * 2;
    #pragma unroll
    for (int im = 0; im < 4; im++) {
        const int m = m0 + wm * 64 + im * 16 + rbase;
        #pragma unroll
        for (int in = 0; in < 4; in++) {
            const int n = n0 + wn * 32 + in * 8 + c2;
            float b0v = 0.0f, b1v = 0.0f;
            if (MODE == 1) { b0v = bias[n]; b1v = bias[n + 1]; }
            float2 v0 = { acc[im][in][0] + b0v, acc[im][in][1] + b1v };
            float2 v1 = { acc[im][in][2] + b0v, acc[im][in][3] + b1v };
            *(float2*)&C[(size_t)m * NTOT + n]       = v0;
            *(float2*)&C[(size_t)(m + 8) * NTOT + n] = v1;
        }
    }
}

// ---------------- LSTM pointwise: preacts -> h_new (fp16) ----------------
__global__ void __launch_bounds__(256) lstm_pointwise(
    const float* __restrict__ cin,
    const float* __restrict__ bf, const float* __restrict__ bi,
    const float* __restrict__ bc, const float* __restrict__ bo) {
    const size_t i4 = (size_t)blockIdx.x * 256 + threadIdx.x;   // grid 16384
    const size_t i = i4 * 4;
    const int n = (int)(i & 4095);
    const size_t m = i >> 12;
    const size_t base = m * NTOT_GATES + n;
    const float4 pf = *(const float4*)&g_pre[base];
    const float4 pi = *(const float4*)&g_pre[base + 4096];
    const float4 pc = *(const float4*)&g_pre[base + 8192];
    const float4 po = *(const float4*)&g_pre[base + 12288];
    const float4 cv = *(const float4*)&cin[i];
    const float f[4]  = { pf.x, pf.y, pf.z, pf.w };
    const float ii[4] = { pi.x, pi.y, pi.z, pi.w };
    const float cd[4] = { pc.x, pc.y, pc.z, pc.w };
    const float oo[4] = { po.x, po.y, po.z, po.w };
    const float cc[4] = { cv.x, cv.y, cv.z, cv.w };
    float hv[4];
    #pragma unroll
    for (int j = 0; j < 4; j++) {
        const float fg = sig(f[j] + bf[n + j]);
        const float ig = sig(ii[j] + bi[n + j]);
        const float cg = tanhf(cd[j] + bc[n + j]);
        const float og = sig(oo[j] + bo[n + j]);
        const float cn = cc[j] * fg + cg * ig;
        hv[j] = tanhf(cn) * og;
    }
    uint2 o;
    o.x = f2h2(hv[0], hv[1]);
    o.y = f2h2(hv[2], hv[3]);
    ((uint2*)g_h16)[i4] = o;
}

// ---------------- softmax (in-place over d_out rows) ----------------
__global__ void __launch_bounds__(256) softmax_kernel(float* __restrict__ d) {
    __shared__ float red[8];
    const size_t row = blockIdx.x;
    const int tid = threadIdx.x, wid = tid >> 5, lid = tid & 31;
    float* p = d + row * (size_t)VDIM + tid * 16;
    float v[16];
    #pragma unroll
    for (int i = 0; i < 4; i++) {
        const float4 q = ((const float4*)p)[i];
        v[i * 4 + 0] = q.x; v[i * 4 + 1] = q.y; v[i * 4 + 2] = q.z; v[i * 4 + 3] = q.w;
    }
    float mx = v[0];
    #pragma unroll
    for (int j = 1; j < 16; j++) mx = fmaxf(mx, v[j]);
    #pragma unroll
    for (int o = 16; o > 0; o >>= 1) mx = fmaxf(mx, __shfl_xor_sync(~0u, mx, o));
    if (lid == 0) red[wid] = mx;
    __syncthreads();
    mx = red[0];
    #pragma unroll
    for (int k = 1; k < 8; k++) mx = fmaxf(mx, red[k]);
    float s = 0.0f;
    #pragma unroll
    for (int j = 0; j < 16; j++) { v[j] = expf(v[j] - mx); s += v[j]; }
    #pragma unroll
    for (int o = 16; o > 0; o >>= 1) s += __shfl_xor_sync(~0u, s, o);
    __syncthreads();
    if (lid == 0) red[wid] = s;
    __syncthreads();
    float tot = 0.0f;
    #pragma unroll
    for (int k = 0; k < 8; k++) tot += red[k];
    const float inv = 1.0f / tot;
    #pragma unroll
    for (int i = 0; i < 4; i++) {
        float4 q;
        q.x = v[i * 4 + 0] * inv; q.y = v[i * 4 + 1] * inv;
        q.z = v[i * 4 + 2] * inv; q.w = v[i * 4 + 3] * inv;
        ((float4*)p)[i] = q;
    }
}

// ---------------- launch ----------------
extern "C" void kernel_launch(void* const* d_in, const int* in_sizes, int n_in,
                              void* d_out, int out_size) {
    const float* x    = (const float*)d_in[0];
    const float* h    = (const float*)d_in[1];
    const float* c    = (const float*)d_in[2];
    const float* Wf   = (const float*)d_in[3];
    const float* bf   = (const float*)d_in[4];
    const float* Wi   = (const float*)d_in[5];
    const float* bi   = (const float*)d_in[6];
    const float* Wc   = (const float*)d_in[7];
    const float* bc   = (const float*)d_in[8];
    const float* Wo   = (const float*)d_in[9];
    const float* bo   = (const float*)d_in[10];
    const float* Wout = (const float*)d_in[11];
    const float* bout = (const float*)d_in[12];
    float* out = (float*)d_out;

    cudaFuncSetAttribute(gemm_f16<0>, cudaFuncAttributeMaxDynamicSharedMemorySize, 131072);
    cudaFuncSetAttribute(gemm_f16<1>, cudaFuncAttributeMaxDynamicSharedMemorySize, 131072);

    pack_xh<<<16384, 256>>>(x, h);
    conv_w<<<16384, 256>>>(Wf, 0);
    conv_w<<<16384, 256>>>(Wi, 1);
    conv_w<<<16384, 256>>>(Wc, 2);
    conv_w<<<16384, 256>>>(Wo, 3);
    conv_w<<<8192, 256>>>(Wout, 4);

    gemm_f16<0><<<dim3(BDIM / 128, NTOT_GATES / 128), 256, 131072>>>(nullptr, nullptr);
    lstm_pointwise<<<16384, 256>>>(c, bf, bi, bc, bo);
    gemm_f16<1><<<dim3(BDIM / 128, VDIM / 128), 256, 131072>>>(out, bout);
    softmax_kernel<<<BDIM, 256>>>(out);
}

// round 5
// speedup vs baseline: 1.0581x; 1.0581x over previous
#include <cuda_runtime.h>
#include <cuda_fp16.h>
#include <cstdint>
#include <math.h>

#define DEVINL __device__ __forceinline__

// ---------------- dims ----------------
constexpr int BDIM = 4096, HDIM = 4096, VDIM = 4096;
constexpr int KH_GATES = VDIM + HDIM;   // 8192
constexpr int NTOT_GATES = 4 * HDIM;    // 16384 (f,i,c,o stacked)

// GEMM tiling
constexpr int CTM = 256, CTN = 128;     // CTA tile
constexpr int STG_A = CTM * 128;        // 32768 B (256 rows x 128B)
constexpr int STG_B = CTN * 128;        // 16384 B
constexpr int STG   = STG_A + STG_B;    // 49152 B per stage
constexpr int NSTG  = 4;                // 196608 B total

// ---------------- scratch (__device__ globals; no allocations) ----------------
__device__ __half g_xh  [(size_t)BDIM * KH_GATES];          // 64 MB
__device__ __half g_wall[(size_t)4 * HDIM * KH_GATES];      // 256 MB
__device__ __half g_wout[(size_t)VDIM * HDIM];              // 32 MB
__device__ float  g_pre [(size_t)BDIM * NTOT_GATES];        // 256 MB
__device__ __half g_h16 [(size_t)BDIM * HDIM];              // 32 MB

// ---------------- small helpers ----------------
DEVINL uint32_t smem_u32(const void* p) {
    uint32_t a;
    asm("{ .reg .u64 t; cvta.to.shared.u64 t, %1; cvt.u32.u64 %0, t; }"
        : "=r"(a) : "l"(p));
    return a;
}
DEVINL void cp16(uint32_t dst, const void* src) {
    asm volatile("cp.async.cg.shared.global [%0], [%1], 16;"
                 :: "r"(dst), "l"(__cvta_generic_to_global(src)) : "memory");
}
DEVINL void ldsm4(uint32_t (&r)[4], uint32_t addr) {
    asm volatile("ldmatrix.sync.aligned.m8n8.x4.shared.b16 {%0,%1,%2,%3}, [%4];"
                 : "=r"(r[0]), "=r"(r[1]), "=r"(r[2]), "=r"(r[3]) : "r"(addr));
}
DEVINL void mma16816(float (&d)[4], const uint32_t (&a)[4], uint32_t b0, uint32_t b1) {
    asm volatile(
        "mma.sync.aligned.m16n8k16.row.col.f32.f16.f16.f32 "
        "{%0,%1,%2,%3},{%4,%5,%6,%7},{%8,%9},{%0,%1,%2,%3};"
        : "+f"(d[0]), "+f"(d[1]), "+f"(d[2]), "+f"(d[3])
        : "r"(a[0]), "r"(a[1]), "r"(a[2]), "r"(a[3]), "r"(b0), "r"(b1));
}
DEVINL uint32_t f2h2(float a, float b) {
    __half2 t = __floats2half2_rn(a, b);
    return *reinterpret_cast<uint32_t*>(&t);
}
DEVINL float sig(float x) { return 1.0f / (1.0f + expf(-x)); }

// ---------------- conversion kernels ----------------
__global__ void __launch_bounds__(256) pack_xh(const float* __restrict__ x,
                                               const float* __restrict__ h) {
    const size_t o8 = (size_t)blockIdx.x * 256 + threadIdx.x;   // grid 16384
    const int    k8 = (int)(o8 & 1023);
    const size_t m  = o8 >> 10;
    const float* s  = (k8 < 512) ? x + m * VDIM + (size_t)k8 * 8
                                 : h + m * HDIM + (size_t)(k8 - 512) * 8;
    const float4 a = *(const float4*)s;
    const float4 b = *(const float4*)(s + 4);
    uint4 o;
    o.x = f2h2(a.x, a.y); o.y = f2h2(a.z, a.w);
    o.z = f2h2(b.x, b.y); o.w = f2h2(b.z, b.w);
    ((uint4*)g_xh)[o8] = o;
}

__global__ void __launch_bounds__(256) conv_w(const float* __restrict__ s, int which) {
    const size_t i8 = (size_t)blockIdx.x * 256 + threadIdx.x;
    __half* dst = (which < 4) ? g_wall + ((size_t)which << 25) : g_wout;
    const float4 a = *(const float4*)(s + i8 * 8);
    const float4 b = *(const float4*)(s + i8 * 8 + 4);
    uint4 o;
    o.x = f2h2(a.x, a.y); o.y = f2h2(a.z, a.w);
    o.z = f2h2(b.x, b.y); o.w = f2h2(b.z, b.w);
    ((uint4*)dst)[i8] = o;
}

// ---------------- GEMM: C[M,NTOT] = A[M,K] * B[NTOT,K]^T (fp16 in, fp32 acc) ----
// CTA tile 256x128, warp grid 4(M) x 2(N), warp tile 64x64, K-tile 64 halves.
// MODE 0: A=g_xh  K=8192, B=g_wall NTOT=16384, C=g_pre     (no bias)
// MODE 1: A=g_h16 K=4096, B=g_wout NTOT=4096,  C=out+bias
template <int MODE>
__global__ void __launch_bounds__(256, 1) gemm_f16(float* __restrict__ Cext,
                                                   const float* __restrict__ bias) {
    constexpr int KH     = MODE ? HDIM : KH_GATES;
    constexpr int NTOT   = MODE ? VDIM : NTOT_GATES;
    constexpr int KTILES = KH / 64;
    const __half* A  = MODE ? g_h16 : g_xh;
    const __half* Bw = MODE ? g_wout : g_wall;
    float* C = MODE ? Cext : g_pre;

    extern __shared__ char smem[];
    const uint32_t sb = smem_u32(smem);
    const int tid = threadIdx.x, lane = tid & 31, wid = tid >> 5;
    const int wm = wid & 3, wn = wid >> 2;         // 4(M) x 2(N)
    const int m0 = blockIdx.x * CTM, n0 = blockIdx.y * CTN;

    auto load_stage = [&](int kt, int s) {
        const int kg = kt * 64;                    // halves
        #pragma unroll
        for (int it = 0; it < 12; it++) {
            const int chunk = tid + it * 256;      // 3072 x 16B per stage
            uint32_t dst;
            const __half* src;
            if (chunk < 2048) {                    // A: 256 rows x 8 chunks
                const int row = chunk >> 3, cc = chunk & 7;
                src = A + (size_t)(m0 + row) * KH + kg + cc * 8;
                dst = sb + s * STG + row * 128 + (uint32_t)((cc ^ (row & 7)) << 4);
            } else {                               // B: 128 rows x 8 chunks
                const int w = chunk - 2048;
                const int row = w >> 3, cc = w & 7;
                src = Bw + (size_t)(n0 + row) * KH + kg + cc * 8;
                dst = sb + s * STG + STG_A + row * 128 + (uint32_t)((cc ^ (row & 7)) << 4);
            }
            cp16(dst, src);
        }
        asm volatile("cp.async.commit_group;" ::: "memory");
    };

    load_stage(0, 0); load_stage(1, 1); load_stage(2, 2);

    // ldmatrix bases (row & 7 == lane & 7 for all fragments)
    uint32_t a_base[4], b_base[4];
    #pragma unroll
    for (int im = 0; im < 4; im++)
        a_base[im] = sb + (uint32_t)((wm * 64 + im * 16 + (lane & 15)) * 128);
    #pragma unroll
    for (int ig = 0; ig < 4; ig++)
        b_base[ig] = sb + STG_A +
            (uint32_t)((wn * 64 + ig * 16 + (lane & 7) + ((lane >> 1) & 8)) * 128);
    const int a_hi = lane >> 4;
    const int b_hi = (lane >> 3) & 1;
    const int sxor = lane & 7;

    float acc[4][8][4];
    #pragma unroll
    for (int i = 0; i < 4; i++)
        #pragma unroll
        for (int j = 0; j < 8; j++)
            #pragma unroll
            for (int k = 0; k < 4; k++) acc[i][j][k] = 0.0f;

    for (int kt = 0; kt < KTILES; kt++) {
        asm volatile("cp.async.wait_group 2;" ::: "memory");
        __syncthreads();
        if (kt + 3 < KTILES) load_stage(kt + 3, (kt + 3) & 3);
        else asm volatile("cp.async.commit_group;" ::: "memory");

        const uint32_t soff = (uint32_t)((kt & 3) * STG);
        #pragma unroll
        for (int ks = 0; ks < 4; ks++) {
            uint32_t a[4][4], b[4][4];
            #pragma unroll
            for (int im = 0; im < 4; im++)
                ldsm4(a[im], a_base[im] + soff + (uint32_t)(((ks * 2 + a_hi) ^ sxor) << 4));
            #pragma unroll
            for (int ig = 0; ig < 4; ig++)
                ldsm4(b[ig], b_base[ig] + soff + (uint32_t)(((ks * 2 + b_hi) ^ sxor) << 4));
            #pragma unroll
            for (int im = 0; im < 4; im++)
                #pragma unroll
                for (int ig = 0; ig < 4; ig++) {
                    mma16816(acc[im][2 * ig + 0], a[im], b[ig][0], b[ig][1]);
                    mma16816(acc[im][2 * ig + 1], a[im], b[ig][2], b[ig][3]);
                }
        }
    }

    const int rbase = lane >> 2, c2 = (lane & 3) * 2;
    #pragma unroll
    for (int im = 0; im < 4; im++) {
        const int m = m0 + wm * 64 + im * 16 + rbase;
        #pragma unroll
        for (int in = 0; in < 8; in++) {
            const int n = n0 + wn * 64 + in * 8 + c2;
            float b0v = 0.0f, b1v = 0.0f;
            if (MODE == 1) { b0v = bias[n]; b1v = bias[n + 1]; }
            float2 v0 = { acc[im][in][0] + b0v, acc[im][in][1] + b1v };
            float2 v1 = { acc[im][in][2] + b0v, acc[im][in][3] + b1v };
            *(float2*)&C[(size_t)m * NTOT + n]       = v0;
            *(float2*)&C[(size_t)(m + 8) * NTOT + n] = v1;
        }
    }
}

// ---------------- LSTM pointwise: preacts -> h_new (fp16) ----------------
__global__ void __launch_bounds__(256) lstm_pointwise(
    const float* __restrict__ cin,
    const float* __restrict__ bf, const float* __restrict__ bi,
    const float* __restrict__ bc, const float* __restrict__ bo) {
    const size_t i4 = (size_t)blockIdx.x * 256 + threadIdx.x;   // grid 16384
    const size_t i = i4 * 4;
    const int n = (int)(i & 4095);
    const size_t m = i >> 12;
    const size_t base = m * NTOT_GATES + n;
    const float4 pf = *(const float4*)&g_pre[base];
    const float4 pi = *(const float4*)&g_pre[base + 4096];
    const float4 pc = *(const float4*)&g_pre[base + 8192];
    const float4 po = *(const float4*)&g_pre[base + 12288];
    const float4 cv = *(const float4*)&cin[i];
    const float f[4]  = { pf.x, pf.y, pf.z, pf.w };
    const float ii[4] = { pi.x, pi.y, pi.z, pi.w };
    const float cd[4] = { pc.x, pc.y, pc.z, pc.w };
    const float oo[4] = { po.x, po.y, po.z, po.w };
    const float cc[4] = { cv.x, cv.y, cv.z, cv.w };
    float hv[4];
    #pragma unroll
    for (int j = 0; j < 4; j++) {
        const float fg = sig(f[j] + bf[n + j]);
        const float ig = sig(ii[j] + bi[n + j]);
        const float cg = tanhf(cd[j] + bc[n + j]);
        const float og = sig(oo[j] + bo[n + j]);
        const float cn = cc[j] * fg + cg * ig;
        hv[j] = tanhf(cn) * og;
    }
    uint2 o;
    o.x = f2h2(hv[0], hv[1]);
    o.y = f2h2(hv[2], hv[3]);
    ((uint2*)g_h16)[i4] = o;
}

// ---------------- softmax (in-place over d_out rows) ----------------
__global__ void __launch_bounds__(256) softmax_kernel(float* __restrict__ d) {
    __shared__ float red[8];
    const size_t row = blockIdx.x;
    const int tid = threadIdx.x, wid = tid >> 5, lid = tid & 31;
    float* p = d + row * (size_t)VDIM + tid * 16;
    float v[16];
    #pragma unroll
    for (int i = 0; i < 4; i++) {
        const float4 q = ((const float4*)p)[i];
        v[i * 4 + 0] = q.x; v[i * 4 + 1] = q.y; v[i * 4 + 2] = q.z; v[i * 4 + 3] = q.w;
    }
    float mx = v[0];
    #pragma unroll
    for (int j = 1; j < 16; j++) mx = fmaxf(mx, v[j]);
    #pragma unroll
    for (int o = 16; o > 0; o >>= 1) mx = fmaxf(mx, __shfl_xor_sync(~0u, mx, o));
    if (lid == 0) red[wid] = mx;
    __syncthreads();
    mx = red[0];
    #pragma unroll
    for (int k = 1; k < 8; k++) mx = fmaxf(mx, red[k]);
    float s = 0.0f;
    #pragma unroll
    for (int j = 0; j < 16; j++) { v[j] = expf(v[j] - mx); s += v[j]; }
    #pragma unroll
    for (int o = 16; o > 0; o >>= 1) s += __shfl_xor_sync(~0u, s, o);
    __syncthreads();
    if (lid == 0) red[wid] = s;
    __syncthreads();
    float tot = 0.0f;
    #pragma unroll
    for (int k = 0; k < 8; k++) tot += red[k];
    const float inv = 1.0f / tot;
    #pragma unroll
    for (int i = 0; i < 4; i++) {
        float4 q;
        q.x = v[i * 4 + 0] * inv; q.y = v[i * 4 + 1] * inv;
        q.z = v[i * 4 + 2] * inv; q.w = v[i * 4 + 3] * inv;
        ((float4*)p)[i] = q;
    }
}

// ---------------- launch ----------------
extern "C" void kernel_launch(void* const* d_in, const int* in_sizes, int n_in,
                              void* d_out, int out_size) {
    const float* x    = (const float*)d_in[0];
    const float* h    = (const float*)d_in[1];
    const float* c    = (const float*)d_in[2];
    const float* Wf   = (const float*)d_in[3];
    const float* bf   = (const float*)d_in[4];
    const float* Wi   = (const float*)d_in[5];
    const float* bi   = (const float*)d_in[6];
    const float* Wc   = (const float*)d_in[7];
    const float* bc   = (const float*)d_in[8];
    const float* Wo   = (const float*)d_in[9];
    const float* bo   = (const float*)d_in[10];
    const float* Wout = (const float*)d_in[11];
    const float* bout = (const float*)d_in[12];
    float* out = (float*)d_out;

    cudaFuncSetAttribute(gemm_f16<0>, cudaFuncAttributeMaxDynamicSharedMemorySize,
                         NSTG * STG);
    cudaFuncSetAttribute(gemm_f16<1>, cudaFuncAttributeMaxDynamicSharedMemorySize,
                         NSTG * STG);

    // launch order puts gates GEMM at index 6 so ncu (-s 5 -c 1) profiles it
    pack_xh<<<16384, 256>>>(x, h);
    conv_w<<<16384, 256>>>(Wf, 0);
    conv_w<<<16384, 256>>>(Wi, 1);
    conv_w<<<16384, 256>>>(Wc, 2);
    conv_w<<<16384, 256>>>(Wo, 3);
    gemm_f16<0><<<dim3(BDIM / CTM, NTOT_GATES / CTN), 256, NSTG * STG>>>(nullptr, nullptr);
    conv_w<<<8192, 256>>>(Wout, 4);
    lstm_pointwise<<<16384, 256>>>(c, bf, bi, bc, bo);
    gemm_f16<1><<<dim3(BDIM / CTM, VDIM / CTN), 256, NSTG * STG>>>(out, bout);
    softmax_kernel<<<BDIM, 256>>>(out);
}